// round 14
// baseline (speedup 1.0000x reference)
#include <cuda_runtime.h>
#include <cuda_bf16.h>
#include <math.h>
#include <stdint.h>

#define Bsz 2
#define Lseq 1024
#define Dm 768
#define NLAYERS 4
#define DSTATE 16
#define DCONV 4
#define DINNER 1536
#define DTRANK 48
#define NCLS 10
#define XDBL 80          // DT_RANK + 2*DSTATE
#define BL (Bsz*Lseq)    // 2048
#define NCH 32           // scan chunks
#define CLEN (Lseq/NCH)  // 32

typedef __nv_bfloat16 bf16;

// ---------------- scratch (device globals; no runtime allocation) ----------
__device__ float g_res  [BL*Dm];
__device__ bf16  g_xnh  [BL*Dm];
__device__ bf16  g_xnl  [BL*Dm];
__device__ float g_xz   [BL*2*DINNER];
__device__ float g_xc   [BL*DINNER];
__device__ bf16  g_xch  [BL*DINNER];
__device__ bf16  g_xcl  [BL*DINNER];
__device__ float g_xdbl [BL*XDBL];
__device__ float g_delta[BL*DINNER];
__device__ bf16  g_yh   [BL*DINNER];
__device__ bf16  g_yl   [BL*DINNER];
// chunked-scan state: layout [b][c][n][d]
__device__ float g_P [Bsz*NCH*DSTATE*DINNER];
__device__ float g_q [Bsz*NCH*DSTATE*DINNER];
__device__ float g_hs[Bsz*NCH*DSTATE*DINNER];
// split weights (converted each call; deterministic)
__device__ bf16  g_wih  [NLAYERS*2*DINNER*Dm];
__device__ bf16  g_wil  [NLAYERS*2*DINNER*Dm];
__device__ bf16  g_woh  [NLAYERS*Dm*DINNER];
__device__ bf16  g_wol  [NLAYERS*Dm*DINNER];
__device__ bf16  g_wxh  [NLAYERS*XDBL*DINNER];
__device__ bf16  g_wxl  [NLAYERS*XDBL*DINNER];

// ---------------- fp32 -> bf16 hi/lo split (vectorized) ---------------------
__global__ void cvt_split_kernel(const float* __restrict__ src,
    bf16* __restrict__ hi, bf16* __restrict__ lo, int n) {
    int i4 = (blockIdx.x * blockDim.x + threadIdx.x) * 4;
    int stride = gridDim.x * blockDim.x * 4;
    for (; i4 < n; i4 += stride) {
        float4 x = *(const float4*)(src + i4);
        bf16 hb[4], lb[4];
        hb[0] = __float2bfloat16(x.x); lb[0] = __float2bfloat16(x.x - __bfloat162float(hb[0]));
        hb[1] = __float2bfloat16(x.y); lb[1] = __float2bfloat16(x.y - __bfloat162float(hb[1]));
        hb[2] = __float2bfloat16(x.z); lb[2] = __float2bfloat16(x.z - __bfloat162float(hb[2]));
        hb[3] = __float2bfloat16(x.w); lb[3] = __float2bfloat16(x.w - __bfloat162float(hb[3]));
        *(uint2*)(hi + i4) = *(uint2*)hb;
        *(uint2*)(lo + i4) = *(uint2*)lb;
    }
}

// ---------------- rmsnorm: one block per token, emits bf16 hi/lo -----------
__global__ __launch_bounds__(256) void rmsnorm_kernel(const float* __restrict__ x,
    const float* __restrict__ w, bf16* __restrict__ oh, bf16* __restrict__ ol) {
    __shared__ float red[256];
    int row = blockIdx.x, tid = threadIdx.x;
    const float* xr = x + (size_t)row * Dm;
    float v0 = xr[tid], v1 = xr[tid + 256], v2 = xr[tid + 512];
    red[tid] = v0*v0 + v1*v1 + v2*v2;
    __syncthreads();
    for (int s = 128; s > 0; s >>= 1) {
        if (tid < s) red[tid] += red[tid + s];
        __syncthreads();
    }
    float rinv = rsqrtf(red[0] * (1.0f / Dm) + 1e-6f);
    bf16* ohr = oh + (size_t)row * Dm;
    bf16* olr = ol + (size_t)row * Dm;
#pragma unroll
    for (int q = 0; q < 3; q++) {
        float v = (q == 0 ? v0 : q == 1 ? v1 : v2) * rinv * w[tid + q * 256];
        bf16 h = __float2bfloat16(v);
        ohr[tid + q * 256] = h;
        olr[tid + q * 256] = __float2bfloat16(v - __bfloat162float(h));
    }
}

// ---------------- MMA / ldmatrix / cp.async helpers -------------------------
__device__ __forceinline__ void mma_bf16(float& c0, float& c1, float& c2, float& c3,
    unsigned a0, unsigned a1, unsigned a2, unsigned a3, unsigned b0, unsigned b1) {
    asm volatile("mma.sync.aligned.m16n8k16.row.col.f32.bf16.bf16.f32 "
        "{%0,%1,%2,%3},{%4,%5,%6,%7},{%8,%9},{%0,%1,%2,%3};\n"
        : "+f"(c0), "+f"(c1), "+f"(c2), "+f"(c3)
        : "r"(a0), "r"(a1), "r"(a2), "r"(a3), "r"(b0), "r"(b1));
}

__device__ __forceinline__ void ldsm4(unsigned& r0, unsigned& r1, unsigned& r2,
                                      unsigned& r3, unsigned a) {
    asm volatile("ldmatrix.sync.aligned.m8n8.x4.shared.b16 {%0,%1,%2,%3}, [%4];\n"
        : "=r"(r0), "=r"(r1), "=r"(r2), "=r"(r3) : "r"(a));
}

__device__ __forceinline__ void cp16(unsigned dst, const void* src) {
    asm volatile("cp.async.cg.shared.global [%0], [%1], 16;\n" :: "r"(dst), "l"(src));
}
#define CP_COMMIT asm volatile("cp.async.commit_group;\n")
#define CP_WAIT1  asm volatile("cp.async.wait_group 1;\n")

// ---------------- bf16x2-split tensor-core GEMM (128x128 tiles) ------------
// C[M,N] (+)= A[M,ld] * W[N,ld]^T restricted to K-slice [z*Klen, (z+1)*Klen).
// acc==0: plain store (gridDim.z must be 1)
// acc==1: atomicAdd epilogue (split-K safe; C must be pre-initialized)
#define GSPAD 40                         // bf16 per smem row (80B, conflict-free)
#define ARRB  (128*GSPAD*2)              // bytes per operand array  = 10240
#define STAGEB (4*ARRB)                  // bytes per pipeline stage = 40960
#define GSTAGES 2                        // 80KB total -> 2 CTAs/SM

__global__ __launch_bounds__(256, 2) void gemm_bf16x2(
    const bf16* __restrict__ Ah, const bf16* __restrict__ Al,
    const bf16* __restrict__ Wh, const bf16* __restrict__ Wl,
    float* __restrict__ C, int N, int ld, int Klen, int acc) {
    extern __shared__ __align__(16) bf16 dsm[];
    const unsigned sb = (unsigned)__cvta_generic_to_shared(dsm);
    const int tid = threadIdx.x;
    const int bm = blockIdx.y * 128, bn = blockIdx.x * 128;
    const int kbase = blockIdx.z * Klen;
    const int warp = tid >> 5, lane = tid & 31;
    const int wm = (warp >> 2) * 64, wn = (warp & 3) * 32;
    const int g = lane >> 2, cq = lane & 3;

    float accr[4][4][4];
#pragma unroll
    for (int mi = 0; mi < 4; mi++)
#pragma unroll
        for (int ni = 0; ni < 4; ni++)
#pragma unroll
            for (int q = 0; q < 4; q++) accr[mi][ni][q] = 0.0f;

    const int r0 = tid >> 1;
    const int q0 = (tid & 1) * 16;
    const unsigned off0 = (unsigned)(r0 * (GSPAD * 2) + q0 * 2);
    const bf16* pAh = Ah + (size_t)(bm + r0) * ld + kbase + q0;
    const bf16* pAl = Al + (size_t)(bm + r0) * ld + kbase + q0;
    const bf16* pWh = Wh + (size_t)(bn + r0) * ld + kbase + q0;
    const bf16* pWl = Wl + (size_t)(bn + r0) * ld + kbase + q0;

    const int rA   = wm + (lane & 15);
    const unsigned aoff = (unsigned)(rA * (GSPAD * 2) + ((lane >> 4) & 1) * 16);
    const int rB   = wn + (lane & 7) + ((lane & 16) >> 1);
    const unsigned boff = (unsigned)(2 * ARRB + rB * (GSPAD * 2) + ((lane & 8) ? 16 : 0));

#define G_ISSUE(s, kk) do { unsigned stg = sb + (unsigned)(s) * STAGEB;          \
        cp16(stg + off0,             pAh + (kk));                                \
        cp16(stg + off0 + 16,        pAh + (kk) + 8);                            \
        cp16(stg + ARRB + off0,      pAl + (kk));                                \
        cp16(stg + ARRB + off0 + 16, pAl + (kk) + 8);                            \
        cp16(stg + 2*ARRB + off0,    pWh + (kk));                                \
        cp16(stg + 2*ARRB + off0+16, pWh + (kk) + 8);                            \
        cp16(stg + 3*ARRB + off0,    pWl + (kk));                                \
        cp16(stg + 3*ARRB + off0+16, pWl + (kk) + 8); } while (0)

    G_ISSUE(0, 0);  CP_COMMIT;
    G_ISSUE(1, 32); CP_COMMIT;

    int cur = 0;
    for (int k0 = 0; k0 < Klen; k0 += 32) {
        CP_WAIT1;
        __syncthreads();

        const unsigned st = sb + (unsigned)cur * STAGEB;
#pragma unroll
        for (int ks = 0; ks < 2; ks++) {
            const unsigned ko = (unsigned)(ks * 32);
            unsigned bh[4][2], bl[4][2];
            ldsm4(bh[0][0], bh[0][1], bh[1][0], bh[1][1], st + boff + ko);
            ldsm4(bh[2][0], bh[2][1], bh[3][0], bh[3][1], st + boff + 1280 + ko);
            ldsm4(bl[0][0], bl[0][1], bl[1][0], bl[1][1], st + boff + ARRB + ko);
            ldsm4(bl[2][0], bl[2][1], bl[3][0], bl[3][1], st + boff + ARRB + 1280 + ko);
#pragma unroll
            for (int mi = 0; mi < 4; mi++) {
                unsigned a0, a1, a2, a3, l0, l1, l2, l3;
                ldsm4(a0, a1, a2, a3, st + aoff + (unsigned)(mi * 1280) + ko);
                ldsm4(l0, l1, l2, l3, st + aoff + ARRB + (unsigned)(mi * 1280) + ko);
#pragma unroll
                for (int ni = 0; ni < 4; ni++) {
                    float* c = accr[mi][ni];
                    mma_bf16(c[0], c[1], c[2], c[3], a0, a1, a2, a3, bh[ni][0], bh[ni][1]);
                    mma_bf16(c[0], c[1], c[2], c[3], a0, a1, a2, a3, bl[ni][0], bl[ni][1]);
                    mma_bf16(c[0], c[1], c[2], c[3], l0, l1, l2, l3, bh[ni][0], bh[ni][1]);
                }
            }
        }
        __syncthreads();
        int kn = k0 + 64;
        if (kn < Klen) G_ISSUE(cur, kn);
        CP_COMMIT;
        cur ^= 1;
    }

#pragma unroll
    for (int mi = 0; mi < 4; mi++) {
#pragma unroll
        for (int ni = 0; ni < 4; ni++) {
            int row = bm + wm + mi * 16 + g;
            int col = bn + wn + ni * 8 + cq * 2;
            float* p0 = &C[(size_t)row * N + col];
            float* p1 = &C[(size_t)(row + 8) * N + col];
            float* c = accr[mi][ni];
            if (acc) {
                atomicAdd(p0,     c[0]); atomicAdd(p0 + 1, c[1]);
                atomicAdd(p1,     c[2]); atomicAdd(p1 + 1, c[3]);
            } else {
                *(float2*)p0 = make_float2(c[0], c[1]);
                *(float2*)p1 = make_float2(c[2], c[3]);
            }
        }
    }
}
#undef G_ISSUE

// ---------------- x_proj tensor-core GEMM: [2048,80] = xc @ W^T -------------
#define XA_ARRB (128*GSPAD*2)            // 10240
#define XB_ARRB (80*GSPAD*2)             // 6400
#define XSTAGEB (2*XA_ARRB + 2*XB_ARRB)  // 33280
#define XSPLIT  4
#define XKSL    (DINNER/XSPLIT)          // 384

__global__ __launch_bounds__(256) void xproj_tc(
    const bf16* __restrict__ Ah, const bf16* __restrict__ Al,
    const bf16* __restrict__ Wh, const bf16* __restrict__ Wl,
    float* __restrict__ out) {
    extern __shared__ __align__(16) bf16 dsm[];
    const unsigned sb = (unsigned)__cvta_generic_to_shared(dsm);
    const int tid = threadIdx.x;
    const int bm = blockIdx.y * 128;
    const int kbase = blockIdx.x * XKSL;
    const int warp = tid >> 5, lane = tid & 31;
    const int g = lane >> 2, cq = lane & 3;

    float accr[10][4];
#pragma unroll
    for (int ni = 0; ni < 10; ni++)
#pragma unroll
        for (int q = 0; q < 4; q++) accr[ni][q] = 0.0f;

    const int r0 = tid >> 1;
    const int q0 = (tid & 1) * 16;
    const unsigned offA = (unsigned)(r0 * (GSPAD * 2) + q0 * 2);
    const bf16* pAh = Ah + (size_t)(bm + r0) * DINNER + kbase + q0;
    const bf16* pAl = Al + (size_t)(bm + r0) * DINNER + kbase + q0;
    const bf16* pWh = Wh + (size_t)r0 * DINNER + kbase + q0;   // valid if r0<80
    const bf16* pWl = Wl + (size_t)r0 * DINNER + kbase + q0;

    const unsigned aoff = (unsigned)((warp * 16 + (lane & 15)) * (GSPAD * 2)
                                     + ((lane >> 4) & 1) * 16);
    const unsigned boff = (unsigned)(2 * XA_ARRB
                                     + ((lane & 7) + ((lane & 16) >> 1)) * (GSPAD * 2)
                                     + ((lane & 8) ? 16 : 0));

#define X_ISSUE(s, kk) do { unsigned stg = sb + (unsigned)(s) * XSTAGEB;          \
        cp16(stg + offA,              pAh + (kk));                                \
        cp16(stg + offA + 16,         pAh + (kk) + 8);                            \
        cp16(stg + XA_ARRB + offA,    pAl + (kk));                                \
        cp16(stg + XA_ARRB + offA+16, pAl + (kk) + 8);                            \
        if (tid < 160) {                                                          \
            cp16(stg + 2*XA_ARRB + offA,              pWh + (kk));                \
            cp16(stg + 2*XA_ARRB + offA + 16,         pWh + (kk) + 8);            \
            cp16(stg + 2*XA_ARRB + XB_ARRB + offA,    pWl + (kk));                \
            cp16(stg + 2*XA_ARRB + XB_ARRB + offA+16, pWl + (kk) + 8);            \
        } } while (0)

    X_ISSUE(0, 0);  CP_COMMIT;
    X_ISSUE(1, 32); CP_COMMIT;

    int cur = 0;
    for (int k0 = 0; k0 < XKSL; k0 += 32) {
        CP_WAIT1;
        __syncthreads();
        const unsigned st = sb + (unsigned)cur * XSTAGEB;
#pragma unroll
        for (int ks = 0; ks < 2; ks++) {
            const unsigned ko = (unsigned)(ks * 32);
            unsigned a0, a1, a2, a3, l0, l1, l2, l3;
            ldsm4(a0, a1, a2, a3, st + aoff + ko);
            ldsm4(l0, l1, l2, l3, st + XA_ARRB + aoff + ko);
#pragma unroll
            for (int p = 0; p < 5; p++) {
                unsigned bh0, bh1, bh2, bh3, bl0, bl1, bl2, bl3;
                ldsm4(bh0, bh1, bh2, bh3, st + boff + (unsigned)(p * 16 * GSPAD * 2) + ko);
                ldsm4(bl0, bl1, bl2, bl3, st + boff + XB_ARRB + (unsigned)(p * 16 * GSPAD * 2) + ko);
                float* c0 = accr[p * 2];
                mma_bf16(c0[0], c0[1], c0[2], c0[3], a0, a1, a2, a3, bh0, bh1);
                mma_bf16(c0[0], c0[1], c0[2], c0[3], a0, a1, a2, a3, bl0, bl1);
                mma_bf16(c0[0], c0[1], c0[2], c0[3], l0, l1, l2, l3, bh0, bh1);
                float* c1 = accr[p * 2 + 1];
                mma_bf16(c1[0], c1[1], c1[2], c1[3], a0, a1, a2, a3, bh2, bh3);
                mma_bf16(c1[0], c1[1], c1[2], c1[3], a0, a1, a2, a3, bl2, bl3);
                mma_bf16(c1[0], c1[1], c1[2], c1[3], l0, l1, l2, l3, bh2, bh3);
            }
        }
        __syncthreads();
        int kn = k0 + 64;
        if (kn < XKSL) X_ISSUE(cur, kn);
        CP_COMMIT;
        cur ^= 1;
    }

    const int row = bm + warp * 16 + g;
#pragma unroll
    for (int ni = 0; ni < 10; ni++) {
        int col = ni * 8 + cq * 2;
        float* c = accr[ni];
        atomicAdd(&out[(size_t)row * XDBL + col],           c[0]);
        atomicAdd(&out[(size_t)row * XDBL + col + 1],       c[1]);
        atomicAdd(&out[(size_t)(row + 8) * XDBL + col],     c[2]);
        atomicAdd(&out[(size_t)(row + 8) * XDBL + col + 1], c[3]);
    }
}
#undef X_ISSUE

// ---------------- causal depthwise conv (width 4) + silu -------------------
// emits fp32 xc (for scans) and bf16 hi/lo (for xproj tensor GEMM)
__global__ void conv_silu_kernel(const float* __restrict__ xz,
    const float* __restrict__ cw, const float* __restrict__ cb,
    float* __restrict__ xc, bf16* __restrict__ xch, bf16* __restrict__ xcl) {
    int idx = blockIdx.x * blockDim.x + threadIdx.x;
    if (idx >= BL * DINNER) return;
    int d  = idx % DINNER;
    int bl = idx / DINNER;
    int t  = bl % Lseq;
    float acc = cb[d];
#pragma unroll
    for (int j = 0; j < DCONV; j++) {
        int tt = t - (DCONV - 1) + j;
        if (tt >= 0)
            acc += cw[d * DCONV + j] *
                   xz[(size_t)(bl - (DCONV - 1) + j) * (2 * DINNER) + d];
    }
    float v = acc / (1.0f + __expf(-acc));
    xc[idx] = v;
    bf16 h = __float2bfloat16(v);
    xch[idx] = h;
    xcl[idx] = __float2bfloat16(v - __bfloat162float(h));
}

// ---------------- dt_proj + softplus ---------------------------------------
__global__ __launch_bounds__(256) void dtproj_kernel(const float* __restrict__ xdbl,
    const float* __restrict__ W, const float* __restrict__ bias,
    float* __restrict__ delta) {
    __shared__ float Xs[64][49];
    __shared__ float Ws[128][49];
    const int bm = blockIdx.x * 64, bn = blockIdx.y * 128;
    const int tid = threadIdx.x, tx = tid & 15, ty = tid >> 4;
    for (int e = tid; e < 64 * 48; e += 256) {
        int r = e / 48, c = e % 48;
        Xs[r][c] = xdbl[(size_t)(bm + r) * XDBL + c];
    }
    for (int e = tid; e < 128 * 48; e += 256) {
        int r = e / 48, c = e % 48;
        Ws[r][c] = W[(size_t)(bn + r) * DTRANK + c];
    }
    __syncthreads();
    float acc[4][8] = {};
    for (int k = 0; k < 48; k++) {
        float a[4], w[8];
#pragma unroll
        for (int rr = 0; rr < 4; rr++) a[rr] = Xs[ty + 16 * rr][k];
#pragma unroll
        for (int cc = 0; cc < 8; cc++) w[cc] = Ws[tx + 16 * cc][k];
#pragma unroll
        for (int rr = 0; rr < 4; rr++)
#pragma unroll
            for (int cc = 0; cc < 8; cc++)
                acc[rr][cc] += a[rr] * w[cc];
    }
#pragma unroll
    for (int rr = 0; rr < 4; rr++)
#pragma unroll
        for (int cc = 0; cc < 8; cc++) {
            int row = bm + ty + 16 * rr, col = bn + tx + 16 * cc;
            float v = acc[rr][cc] + bias[col];
            float sp = (v > 20.0f) ? v : log1pf(__expf(v));
            delta[(size_t)row * DINNER + col] = sp;
        }
}

// ---------------- chunked parallel scan -------------------------------------
__device__ __forceinline__ void pow_ladder(float e1, float* p) {
    float e2 = e1 * e1, e4 = e2 * e2, e8 = e4 * e4;
    p[0] = e1;        p[1] = e2;        p[2] = e2 * e1;   p[3] = e4;
    p[4] = e4 * e1;   p[5] = e4 * e2;   p[6] = e4 * p[2]; p[7] = e8;
    p[8] = e8 * e1;   p[9] = e8 * e2;   p[10] = e8 * p[2]; p[11] = e8 * e4;
    p[12] = e8 * p[4]; p[13] = e8 * p[5]; p[14] = e8 * p[6]; p[15] = e8 * e8;
}

// pass 1: per (b, chunk, d): P[n] = prod p_t[n], q[n] = scan offset
__global__ __launch_bounds__(256) void scan_pass1(const float* __restrict__ delta,
    const float* __restrict__ xc, const float* __restrict__ xdbl,
    const float* __restrict__ A_log,
    float* __restrict__ Pg, float* __restrict__ qg) {
    const int d = blockIdx.x * 256 + threadIdx.x;
    const int c = blockIdx.y, b = blockIdx.z;
    float a[DSTATE];
    bool fast = true;
#pragma unroll
    for (int n = 0; n < DSTATE; n++) a[n] = -expf(A_log[(size_t)d * DSTATE + n]);
#pragma unroll
    for (int n = 1; n < DSTATE; n++)
        fast = fast && (fabsf(a[n] / a[0] - (float)(n + 1)) < 1e-3f);

    __shared__ float Bsh[CLEN][DSTATE];
    for (int e = threadIdx.x; e < CLEN * DSTATE; e += 256) {
        int tt = e >> 4, n = e & 15;
        Bsh[tt][n] = xdbl[(size_t)(b * Lseq + c * CLEN + tt) * XDBL + DTRANK + n];
    }
    __syncthreads();

    float P[DSTATE], q[DSTATE];
#pragma unroll
    for (int n = 0; n < DSTATE; n++) { P[n] = 1.0f; q[n] = 0.0f; }

    for (int ti = 0; ti < CLEN; ti++) {
        const size_t ix = (size_t)(b * Lseq + c * CLEN + ti) * DINNER + d;
        const float dl = delta[ix];
        const float du = dl * xc[ix];
        float p[DSTATE];
        if (fast) pow_ladder(__expf(dl * a[0]), p);
        else {
#pragma unroll
            for (int n = 0; n < DSTATE; n++) p[n] = __expf(dl * a[n]);
        }
#pragma unroll
        for (int n = 0; n < DSTATE; n++) {
            q[n] = p[n] * q[n] + du * Bsh[ti][n];
            P[n] *= p[n];
        }
    }
    const size_t base = ((size_t)(b * NCH + c) * DSTATE) * DINNER + d;
#pragma unroll
    for (int n = 0; n < DSTATE; n++) {
        Pg[base + (size_t)n * DINNER] = P[n];
        qg[base + (size_t)n * DINNER] = q[n];
    }
}

// pass 2: prefix over chunks, parallel over (b, n, d)
__global__ __launch_bounds__(256) void scan_pass2(const float* __restrict__ Pg,
    const float* __restrict__ qg, float* __restrict__ hs) {
    const int idx = blockIdx.x * 256 + threadIdx.x;
    const int b = idx / (DSTATE * DINNER);
    const int rem = idx - b * DSTATE * DINNER;
    float h = 0.0f;
#pragma unroll 4
    for (int c = 0; c < NCH; c++) {
        const size_t o = ((size_t)(b * NCH + c) * DSTATE) * DINNER + rem;
        hs[o] = h;
        h = Pg[o] * h + qg[o];
    }
}

// pass 3: replay chunk from h_start, emit gated y (bf16 hi/lo)
__global__ __launch_bounds__(256) void scan_pass3(const float* __restrict__ delta,
    const float* __restrict__ xc, const float* __restrict__ xdbl,
    const float* __restrict__ xz, const float* __restrict__ A_log,
    const float* __restrict__ Dskip, const float* __restrict__ hs,
    bf16* __restrict__ yh, bf16* __restrict__ yl) {
    const int d = blockIdx.x * 256 + threadIdx.x;
    const int c = blockIdx.y, b = blockIdx.z;
    float a[DSTATE];
    bool fast = true;
#pragma unroll
    for (int n = 0; n < DSTATE; n++) a[n] = -expf(A_log[(size_t)d * DSTATE + n]);
#pragma unroll
    for (int n = 1; n < DSTATE; n++)
        fast = fast && (fabsf(a[n] / a[0] - (float)(n + 1)) < 1e-3f);
    const float dsk = Dskip[d];

    __shared__ float Bsh[CLEN][DSTATE];
    __shared__ float Csh[CLEN][DSTATE];
    for (int e = threadIdx.x; e < CLEN * DSTATE; e += 256) {
        int tt = e >> 4, n = e & 15;
        size_t rb = (size_t)(b * Lseq + c * CLEN + tt) * XDBL;
        Bsh[tt][n] = xdbl[rb + DTRANK + n];
        Csh[tt][n] = xdbl[rb + DTRANK + DSTATE + n];
    }
    __syncthreads();

    float h[DSTATE];
    const size_t base = ((size_t)(b * NCH + c) * DSTATE) * DINNER + d;
#pragma unroll
    for (int n = 0; n < DSTATE; n++) h[n] = hs[base + (size_t)n * DINNER];

    for (int ti = 0; ti < CLEN; ti++) {
        const size_t ix = (size_t)(b * Lseq + c * CLEN + ti) * DINNER + d;
        const float dl = delta[ix];
        const float u  = xc[ix];
        const float du = dl * u;
        float p[DSTATE];
        if (fast) pow_ladder(__expf(dl * a[0]), p);
        else {
#pragma unroll
            for (int n = 0; n < DSTATE; n++) p[n] = __expf(dl * a[n]);
        }
        float ys = 0.0f;
#pragma unroll
        for (int n = 0; n < DSTATE; n++) {
            h[n] = p[n] * h[n] + du * Bsh[ti][n];
            ys += h[n] * Csh[ti][n];
        }
        const float z = xz[(size_t)(b * Lseq + c * CLEN + ti) * (2 * DINNER) + DINNER + d];
        const float g = z / (1.0f + __expf(-z));
        float v = (ys + u * dsk) * g;
        bf16 hi = __float2bfloat16(v);
        yh[ix] = hi;
        yl[ix] = __float2bfloat16(v - __bfloat162float(hi));
    }
}

// ---------------- final norm + MLP head (tiny), fused ----------------------
__device__ __forceinline__ float gelu_exact(float x) {
    return 0.5f * x * (1.0f + erff(x * 0.70710678118654752f));
}

__global__ __launch_bounds__(256) void head_kernel(const float* __restrict__ res,
    const float* __restrict__ fnw, const float* __restrict__ h1w,
    const float* __restrict__ h1b, const float* __restrict__ hnw,
    const float* __restrict__ h2w, const float* __restrict__ h2b,
    float* __restrict__ out) {
    __shared__ float xs[768];
    __shared__ float hsm[768];
    __shared__ float red[256];
    const int b = blockIdx.x;
    const int tid = threadIdx.x;
    const int warp = tid >> 5, lane = tid & 31;

    const float* xr = res + ((size_t)b * Lseq + (Lseq - 1)) * Dm;
    float v0 = xr[tid], v1 = xr[tid + 256], v2 = xr[tid + 512];
    red[tid] = v0 * v0 + v1 * v1 + v2 * v2;
    __syncthreads();
    for (int s = 128; s > 0; s >>= 1) {
        if (tid < s) red[tid] += red[tid + s];
        __syncthreads();
    }
    float rinv = rsqrtf(red[0] * (1.0f / Dm) + 1e-6f);
    xs[tid]       = v0 * rinv * fnw[tid];
    xs[tid + 256] = v1 * rinv * fnw[tid + 256];
    xs[tid + 512] = v2 * rinv * fnw[tid + 512];
    __syncthreads();

    for (int o = warp; o < 768; o += 8) {
        const float* wr = h1w + (size_t)o * 768;
        float p = 0.0f;
        for (int j = lane; j < 768; j += 32) p += wr[j] * xs[j];
#pragma unroll
        for (int s = 16; s > 0; s >>= 1) p += __shfl_xor_sync(0xffffffff, p, s);
        if (lane == 0) hsm[o] = p + h1b[o];
    }
    __syncthreads();

    float h0 = hsm[tid], h1v = hsm[tid + 256], h2v = hsm[tid + 512];
    red[tid] = h0 * h0 + h1v * h1v + h2v * h2v;
    __syncthreads();
    for (int s = 128; s > 0; s >>= 1) {
        if (tid < s) red[tid] += red[tid + s];
        __syncthreads();
    }
    float rinv2 = rsqrtf(red[0] * (1.0f / Dm) + 1e-6f);
    hsm[tid]       = gelu_exact(h0  * rinv2 * hnw[tid]);
    hsm[tid + 256] = gelu_exact(h1v * rinv2 * hnw[tid + 256]);
    hsm[tid + 512] = gelu_exact(h2v * rinv2 * hnw[tid + 512]);
    __syncthreads();

    for (int o = warp; o < NCLS; o += 8) {
        const float* wr = h2w + (size_t)o * 768;
        float p = 0.0f;
        for (int j = lane; j < 768; j += 32) p += wr[j] * hsm[j];
#pragma unroll
        for (int s = 16; s > 0; s >>= 1) p += __shfl_xor_sync(0xffffffff, p, s);
        if (lane == 0) out[b * NCLS + o] = p + h2b[o];
    }
}

// ---------------- launch ---------------------------------------------------
extern "C" void kernel_launch(void* const* d_in, const int* in_sizes, int n_in,
                              void* d_out, int out_size) {
    const float* x           = (const float*)d_in[0];
    const float* norm_w      = (const float*)d_in[1];
    const float* in_proj_w   = (const float*)d_in[2];
    const float* conv_w      = (const float*)d_in[3];
    const float* conv_b      = (const float*)d_in[4];
    const float* x_proj_w    = (const float*)d_in[5];
    const float* dt_proj_w   = (const float*)d_in[6];
    const float* dt_proj_b   = (const float*)d_in[7];
    const float* A_log       = (const float*)d_in[8];
    const float* D_skip      = (const float*)d_in[9];
    const float* out_proj_w  = (const float*)d_in[10];
    const float* final_norm_w= (const float*)d_in[11];
    const float* head1_w     = (const float*)d_in[12];
    const float* head1_b     = (const float*)d_in[13];
    const float* head_norm_w = (const float*)d_in[14];
    const float* head2_w     = (const float*)d_in[15];
    const float* head2_b     = (const float*)d_in[16];
    float* out = (float*)d_out;

    float *res, *xzp, *xcp, *xdblp, *deltap, *Pg, *qg, *hsg;
    bf16 *xnh, *xnl, *xch, *xcl, *yh, *yl, *wih, *wil, *woh, *wol, *wxh, *wxl;
    cudaGetSymbolAddress((void**)&res,    g_res);
    cudaGetSymbolAddress((void**)&xnh,    g_xnh);
    cudaGetSymbolAddress((void**)&xnl,    g_xnl);
    cudaGetSymbolAddress((void**)&xzp,    g_xz);
    cudaGetSymbolAddress((void**)&xcp,    g_xc);
    cudaGetSymbolAddress((void**)&xch,    g_xch);
    cudaGetSymbolAddress((void**)&xcl,    g_xcl);
    cudaGetSymbolAddress((void**)&xdblp,  g_xdbl);
    cudaGetSymbolAddress((void**)&deltap, g_delta);
    cudaGetSymbolAddress((void**)&yh,     g_yh);
    cudaGetSymbolAddress((void**)&yl,     g_yl);
    cudaGetSymbolAddress((void**)&Pg,     g_P);
    cudaGetSymbolAddress((void**)&qg,     g_q);
    cudaGetSymbolAddress((void**)&hsg,    g_hs);
    cudaGetSymbolAddress((void**)&wih,    g_wih);
    cudaGetSymbolAddress((void**)&wil,    g_wil);
    cudaGetSymbolAddress((void**)&woh,    g_woh);
    cudaGetSymbolAddress((void**)&wol,    g_wol);
    cudaGetSymbolAddress((void**)&wxh,    g_wxh);
    cudaGetSymbolAddress((void**)&wxl,    g_wxl);

    // dynamic smem opt-ins (idempotent)
    cudaFuncSetAttribute(gemm_bf16x2,
        cudaFuncAttributeMaxDynamicSharedMemorySize, GSTAGES * STAGEB);
    cudaFuncSetAttribute(xproj_tc,
        cudaFuncAttributeMaxDynamicSharedMemorySize, 2 * XSTAGEB);
    const int GSMEM = GSTAGES * STAGEB;
    const int XSMEM = 2 * XSTAGEB;

    cudaMemcpyAsync(res, x, sizeof(float) * BL * Dm, cudaMemcpyDeviceToDevice, 0);

    cvt_split_kernel<<<592, 256>>>(in_proj_w,  wih, wil, NLAYERS * 2 * DINNER * Dm);
    cvt_split_kernel<<<592, 256>>>(out_proj_w, woh, wol, NLAYERS * Dm * DINNER);
    cvt_split_kernel<<<240, 256>>>(x_proj_w,   wxh, wxl, NLAYERS * XDBL * DINNER);

    for (int i = 0; i < NLAYERS; i++) {
        rmsnorm_kernel<<<BL, 256>>>(res, norm_w + (size_t)i * Dm, xnh, xnl);

        // in_proj: split-K 2-way, atomicAdd onto zeroed xz
        cudaMemsetAsync(xzp, 0, sizeof(float) * BL * 2 * DINNER, 0);
        dim3 g1(2 * DINNER / 128, BL / 128, 2);
        gemm_bf16x2<<<g1, 256, GSMEM>>>(xnh, xnl,
                                 wih + (size_t)i * 2 * DINNER * Dm,
                                 wil + (size_t)i * 2 * DINNER * Dm,
                                 xzp, 2 * DINNER, Dm, Dm / 2, 1);

        conv_silu_kernel<<<BL * DINNER / 256, 256>>>(
            xzp, conv_w + (size_t)i * DINNER * DCONV, conv_b + (size_t)i * DINNER,
            xcp, xch, xcl);

        cudaMemsetAsync(xdblp, 0, sizeof(float) * BL * XDBL, 0);
        dim3 g2(XSPLIT, BL / 128);
        xproj_tc<<<g2, 256, XSMEM>>>(xch, xcl,
                                     wxh + (size_t)i * XDBL * DINNER,
                                     wxl + (size_t)i * XDBL * DINNER, xdblp);

        dim3 g3(BL / 64, DINNER / 128);
        dtproj_kernel<<<g3, 256>>>(xdblp, dt_proj_w + (size_t)i * DINNER * DTRANK,
                                   dt_proj_b + (size_t)i * DINNER, deltap);

        const float* Alog_i = A_log + (size_t)i * DINNER * DSTATE;
        dim3 gs(DINNER / 256, NCH, Bsz);
        scan_pass1<<<gs, 256>>>(deltap, xcp, xdblp, Alog_i, Pg, qg);
        scan_pass2<<<Bsz * DSTATE * DINNER / 256, 256>>>(Pg, qg, hsg);
        scan_pass3<<<gs, 256>>>(deltap, xcp, xdblp, xzp, Alog_i,
                                D_skip + (size_t)i * DINNER, hsg, yh, yl);

        // out_proj: split-K 4-way, atomicAdd accumulation onto residual
        dim3 g5(Dm / 128, BL / 128, 4);
        gemm_bf16x2<<<g5, 256, GSMEM>>>(yh, yl,
                                 woh + (size_t)i * Dm * DINNER,
                                 wol + (size_t)i * Dm * DINNER,
                                 res, Dm, DINNER, DINNER / 4, 1);
    }

    head_kernel<<<Bsz, 256>>>(res, final_norm_w, head1_w, head1_b,
                              head_norm_w, head2_w, head2_b, out);
}

// round 15
// speedup vs baseline: 1.0384x; 1.0384x over previous
#include <cuda_runtime.h>
#include <cuda_bf16.h>
#include <math.h>
#include <stdint.h>

#define Bsz 2
#define Lseq 1024
#define Dm 768
#define NLAYERS 4
#define DSTATE 16
#define DCONV 4
#define DINNER 1536
#define DTRANK 48
#define NCLS 10
#define XDBL 80          // DT_RANK + 2*DSTATE
#define BL (Bsz*Lseq)    // 2048
#define NCH 32           // scan chunks
#define CLEN (Lseq/NCH)  // 32

typedef __nv_bfloat16 bf16;

// ---------------- scratch (device globals; no runtime allocation) ----------
__device__ float g_res  [BL*Dm];
__device__ bf16  g_xnh  [BL*Dm];
__device__ bf16  g_xnl  [BL*Dm];
__device__ float g_xz   [BL*2*DINNER];
__device__ float g_xc   [BL*DINNER];
__device__ bf16  g_xch  [BL*DINNER];
__device__ bf16  g_xcl  [BL*DINNER];
__device__ float g_xdbl [BL*XDBL];
__device__ float g_delta[BL*DINNER];
__device__ bf16  g_yh   [BL*DINNER];
__device__ bf16  g_yl   [BL*DINNER];
// chunked-scan state: layout [b][c][n][d]
__device__ float g_P [Bsz*NCH*DSTATE*DINNER];
__device__ float g_q [Bsz*NCH*DSTATE*DINNER];
__device__ float g_hs[Bsz*NCH*DSTATE*DINNER];
// split weights (converted each call; deterministic)
__device__ bf16  g_wih  [NLAYERS*2*DINNER*Dm];
__device__ bf16  g_wil  [NLAYERS*2*DINNER*Dm];
__device__ bf16  g_woh  [NLAYERS*Dm*DINNER];
__device__ bf16  g_wol  [NLAYERS*Dm*DINNER];
__device__ bf16  g_wxh  [NLAYERS*XDBL*DINNER];
__device__ bf16  g_wxl  [NLAYERS*XDBL*DINNER];

// ---------------- fp32 -> bf16 hi/lo split (vectorized) ---------------------
__global__ void cvt_split_kernel(const float* __restrict__ src,
    bf16* __restrict__ hi, bf16* __restrict__ lo, int n) {
    int i4 = (blockIdx.x * blockDim.x + threadIdx.x) * 4;
    int stride = gridDim.x * blockDim.x * 4;
    for (; i4 < n; i4 += stride) {
        float4 x = *(const float4*)(src + i4);
        bf16 hb[4], lb[4];
        hb[0] = __float2bfloat16(x.x); lb[0] = __float2bfloat16(x.x - __bfloat162float(hb[0]));
        hb[1] = __float2bfloat16(x.y); lb[1] = __float2bfloat16(x.y - __bfloat162float(hb[1]));
        hb[2] = __float2bfloat16(x.z); lb[2] = __float2bfloat16(x.z - __bfloat162float(hb[2]));
        hb[3] = __float2bfloat16(x.w); lb[3] = __float2bfloat16(x.w - __bfloat162float(hb[3]));
        *(uint2*)(hi + i4) = *(uint2*)hb;
        *(uint2*)(lo + i4) = *(uint2*)lb;
    }
}

// ---------------- rmsnorm: one block per token, emits bf16 hi/lo -----------
__global__ __launch_bounds__(256) void rmsnorm_kernel(const float* __restrict__ x,
    const float* __restrict__ w, bf16* __restrict__ oh, bf16* __restrict__ ol) {
    __shared__ float red[256];
    int row = blockIdx.x, tid = threadIdx.x;
    const float* xr = x + (size_t)row * Dm;
    float v0 = xr[tid], v1 = xr[tid + 256], v2 = xr[tid + 512];
    red[tid] = v0*v0 + v1*v1 + v2*v2;
    __syncthreads();
    for (int s = 128; s > 0; s >>= 1) {
        if (tid < s) red[tid] += red[tid + s];
        __syncthreads();
    }
    float rinv = rsqrtf(red[0] * (1.0f / Dm) + 1e-6f);
    bf16* ohr = oh + (size_t)row * Dm;
    bf16* olr = ol + (size_t)row * Dm;
#pragma unroll
    for (int q = 0; q < 3; q++) {
        float v = (q == 0 ? v0 : q == 1 ? v1 : v2) * rinv * w[tid + q * 256];
        bf16 h = __float2bfloat16(v);
        ohr[tid + q * 256] = h;
        olr[tid + q * 256] = __float2bfloat16(v - __bfloat162float(h));
    }
}

// ---------------- MMA / ldmatrix / cp.async helpers -------------------------
__device__ __forceinline__ void mma_bf16(float& c0, float& c1, float& c2, float& c3,
    unsigned a0, unsigned a1, unsigned a2, unsigned a3, unsigned b0, unsigned b1) {
    asm volatile("mma.sync.aligned.m16n8k16.row.col.f32.bf16.bf16.f32 "
        "{%0,%1,%2,%3},{%4,%5,%6,%7},{%8,%9},{%0,%1,%2,%3};\n"
        : "+f"(c0), "+f"(c1), "+f"(c2), "+f"(c3)
        : "r"(a0), "r"(a1), "r"(a2), "r"(a3), "r"(b0), "r"(b1));
}

__device__ __forceinline__ void ldsm4(unsigned& r0, unsigned& r1, unsigned& r2,
                                      unsigned& r3, unsigned a) {
    asm volatile("ldmatrix.sync.aligned.m8n8.x4.shared.b16 {%0,%1,%2,%3}, [%4];\n"
        : "=r"(r0), "=r"(r1), "=r"(r2), "=r"(r3) : "r"(a));
}

__device__ __forceinline__ void cp16(unsigned dst, const void* src) {
    asm volatile("cp.async.cg.shared.global [%0], [%1], 16;\n" :: "r"(dst), "l"(src));
}
#define CP_COMMIT asm volatile("cp.async.commit_group;\n")
#define CP_WAIT1  asm volatile("cp.async.wait_group 1;\n")

// ---------------- bf16x2-split tensor-core GEMM (128x128 tiles) ------------
// C[M,N] (+)= A[M,ld] * W[N,ld]^T restricted to K-slice [z*Klen, (z+1)*Klen).
// acc==0: plain store (gridDim.z must be 1)
// acc==1: atomicAdd epilogue (split-K safe; C must be pre-initialized)
#define GSPAD 40                         // bf16 per smem row (80B, conflict-free)
#define ARRB  (128*GSPAD*2)              // bytes per operand array  = 10240
#define STAGEB (4*ARRB)                  // bytes per pipeline stage = 40960
#define GSTAGES 2                        // 80KB total -> 2 CTAs/SM

__global__ __launch_bounds__(256, 2) void gemm_bf16x2(
    const bf16* __restrict__ Ah, const bf16* __restrict__ Al,
    const bf16* __restrict__ Wh, const bf16* __restrict__ Wl,
    float* __restrict__ C, int N, int ld, int Klen, int acc) {
    extern __shared__ __align__(16) bf16 dsm[];
    const unsigned sb = (unsigned)__cvta_generic_to_shared(dsm);
    const int tid = threadIdx.x;
    const int bm = blockIdx.y * 128, bn = blockIdx.x * 128;
    const int kbase = blockIdx.z * Klen;
    const int warp = tid >> 5, lane = tid & 31;
    const int wm = (warp >> 2) * 64, wn = (warp & 3) * 32;
    const int g = lane >> 2, cq = lane & 3;

    float accr[4][4][4];
#pragma unroll
    for (int mi = 0; mi < 4; mi++)
#pragma unroll
        for (int ni = 0; ni < 4; ni++)
#pragma unroll
            for (int q = 0; q < 4; q++) accr[mi][ni][q] = 0.0f;

    const int r0 = tid >> 1;
    const int q0 = (tid & 1) * 16;
    const unsigned off0 = (unsigned)(r0 * (GSPAD * 2) + q0 * 2);
    const bf16* pAh = Ah + (size_t)(bm + r0) * ld + kbase + q0;
    const bf16* pAl = Al + (size_t)(bm + r0) * ld + kbase + q0;
    const bf16* pWh = Wh + (size_t)(bn + r0) * ld + kbase + q0;
    const bf16* pWl = Wl + (size_t)(bn + r0) * ld + kbase + q0;

    const int rA   = wm + (lane & 15);
    const unsigned aoff = (unsigned)(rA * (GSPAD * 2) + ((lane >> 4) & 1) * 16);
    const int rB   = wn + (lane & 7) + ((lane & 16) >> 1);
    const unsigned boff = (unsigned)(2 * ARRB + rB * (GSPAD * 2) + ((lane & 8) ? 16 : 0));

#define G_ISSUE(s, kk) do { unsigned stg = sb + (unsigned)(s) * STAGEB;          \
        cp16(stg + off0,             pAh + (kk));                                \
        cp16(stg + off0 + 16,        pAh + (kk) + 8);                            \
        cp16(stg + ARRB + off0,      pAl + (kk));                                \
        cp16(stg + ARRB + off0 + 16, pAl + (kk) + 8);                            \
        cp16(stg + 2*ARRB + off0,    pWh + (kk));                                \
        cp16(stg + 2*ARRB + off0+16, pWh + (kk) + 8);                            \
        cp16(stg + 3*ARRB + off0,    pWl + (kk));                                \
        cp16(stg + 3*ARRB + off0+16, pWl + (kk) + 8); } while (0)

    G_ISSUE(0, 0);  CP_COMMIT;
    G_ISSUE(1, 32); CP_COMMIT;

    int cur = 0;
    for (int k0 = 0; k0 < Klen; k0 += 32) {
        CP_WAIT1;
        __syncthreads();

        const unsigned st = sb + (unsigned)cur * STAGEB;
#pragma unroll
        for (int ks = 0; ks < 2; ks++) {
            const unsigned ko = (unsigned)(ks * 32);
            unsigned bh[4][2], bl[4][2];
            ldsm4(bh[0][0], bh[0][1], bh[1][0], bh[1][1], st + boff + ko);
            ldsm4(bh[2][0], bh[2][1], bh[3][0], bh[3][1], st + boff + 1280 + ko);
            ldsm4(bl[0][0], bl[0][1], bl[1][0], bl[1][1], st + boff + ARRB + ko);
            ldsm4(bl[2][0], bl[2][1], bl[3][0], bl[3][1], st + boff + ARRB + 1280 + ko);
#pragma unroll
            for (int mi = 0; mi < 4; mi++) {
                unsigned a0, a1, a2, a3, l0, l1, l2, l3;
                ldsm4(a0, a1, a2, a3, st + aoff + (unsigned)(mi * 1280) + ko);
                ldsm4(l0, l1, l2, l3, st + aoff + ARRB + (unsigned)(mi * 1280) + ko);
#pragma unroll
                for (int ni = 0; ni < 4; ni++) {
                    float* c = accr[mi][ni];
                    mma_bf16(c[0], c[1], c[2], c[3], a0, a1, a2, a3, bh[ni][0], bh[ni][1]);
                    mma_bf16(c[0], c[1], c[2], c[3], a0, a1, a2, a3, bl[ni][0], bl[ni][1]);
                    mma_bf16(c[0], c[1], c[2], c[3], l0, l1, l2, l3, bh[ni][0], bh[ni][1]);
                }
            }
        }
        __syncthreads();
        int kn = k0 + 64;
        if (kn < Klen) G_ISSUE(cur, kn);
        CP_COMMIT;
        cur ^= 1;
    }

#pragma unroll
    for (int mi = 0; mi < 4; mi++) {
#pragma unroll
        for (int ni = 0; ni < 4; ni++) {
            int row = bm + wm + mi * 16 + g;
            int col = bn + wn + ni * 8 + cq * 2;
            float* p0 = &C[(size_t)row * N + col];
            float* p1 = &C[(size_t)(row + 8) * N + col];
            float* c = accr[mi][ni];
            if (acc) {
                atomicAdd(p0,     c[0]); atomicAdd(p0 + 1, c[1]);
                atomicAdd(p1,     c[2]); atomicAdd(p1 + 1, c[3]);
            } else {
                *(float2*)p0 = make_float2(c[0], c[1]);
                *(float2*)p1 = make_float2(c[2], c[3]);
            }
        }
    }
}
#undef G_ISSUE

// ---------------- x_proj tensor-core GEMM: [2048,80] = xc @ W^T -------------
#define XA_ARRB (128*GSPAD*2)            // 10240
#define XB_ARRB (80*GSPAD*2)             // 6400
#define XSTAGEB (2*XA_ARRB + 2*XB_ARRB)  // 33280
#define XSPLIT  8
#define XKSL    (DINNER/XSPLIT)          // 192

__global__ __launch_bounds__(256) void xproj_tc(
    const bf16* __restrict__ Ah, const bf16* __restrict__ Al,
    const bf16* __restrict__ Wh, const bf16* __restrict__ Wl,
    float* __restrict__ out) {
    extern __shared__ __align__(16) bf16 dsm[];
    const unsigned sb = (unsigned)__cvta_generic_to_shared(dsm);
    const int tid = threadIdx.x;
    const int bm = blockIdx.y * 128;
    const int kbase = blockIdx.x * XKSL;
    const int warp = tid >> 5, lane = tid & 31;
    const int g = lane >> 2, cq = lane & 3;

    float accr[10][4];
#pragma unroll
    for (int ni = 0; ni < 10; ni++)
#pragma unroll
        for (int q = 0; q < 4; q++) accr[ni][q] = 0.0f;

    const int r0 = tid >> 1;
    const int q0 = (tid & 1) * 16;
    const unsigned offA = (unsigned)(r0 * (GSPAD * 2) + q0 * 2);
    const bf16* pAh = Ah + (size_t)(bm + r0) * DINNER + kbase + q0;
    const bf16* pAl = Al + (size_t)(bm + r0) * DINNER + kbase + q0;
    const bf16* pWh = Wh + (size_t)r0 * DINNER + kbase + q0;   // valid if r0<80
    const bf16* pWl = Wl + (size_t)r0 * DINNER + kbase + q0;

    const unsigned aoff = (unsigned)((warp * 16 + (lane & 15)) * (GSPAD * 2)
                                     + ((lane >> 4) & 1) * 16);
    const unsigned boff = (unsigned)(2 * XA_ARRB
                                     + ((lane & 7) + ((lane & 16) >> 1)) * (GSPAD * 2)
                                     + ((lane & 8) ? 16 : 0));

#define X_ISSUE(s, kk) do { unsigned stg = sb + (unsigned)(s) * XSTAGEB;          \
        cp16(stg + offA,              pAh + (kk));                                \
        cp16(stg + offA + 16,         pAh + (kk) + 8);                            \
        cp16(stg + XA_ARRB + offA,    pAl + (kk));                                \
        cp16(stg + XA_ARRB + offA+16, pAl + (kk) + 8);                            \
        if (tid < 160) {                                                          \
            cp16(stg + 2*XA_ARRB + offA,              pWh + (kk));                \
            cp16(stg + 2*XA_ARRB + offA + 16,         pWh + (kk) + 8);            \
            cp16(stg + 2*XA_ARRB + XB_ARRB + offA,    pWl + (kk));                \
            cp16(stg + 2*XA_ARRB + XB_ARRB + offA+16, pWl + (kk) + 8);            \
        } } while (0)

    X_ISSUE(0, 0);  CP_COMMIT;
    X_ISSUE(1, 32); CP_COMMIT;

    int cur = 0;
    for (int k0 = 0; k0 < XKSL; k0 += 32) {
        CP_WAIT1;
        __syncthreads();
        const unsigned st = sb + (unsigned)cur * XSTAGEB;
#pragma unroll
        for (int ks = 0; ks < 2; ks++) {
            const unsigned ko = (unsigned)(ks * 32);
            unsigned a0, a1, a2, a3, l0, l1, l2, l3;
            ldsm4(a0, a1, a2, a3, st + aoff + ko);
            ldsm4(l0, l1, l2, l3, st + XA_ARRB + aoff + ko);
#pragma unroll
            for (int p = 0; p < 5; p++) {
                unsigned bh0, bh1, bh2, bh3, bl0, bl1, bl2, bl3;
                ldsm4(bh0, bh1, bh2, bh3, st + boff + (unsigned)(p * 16 * GSPAD * 2) + ko);
                ldsm4(bl0, bl1, bl2, bl3, st + boff + XB_ARRB + (unsigned)(p * 16 * GSPAD * 2) + ko);
                float* c0 = accr[p * 2];
                mma_bf16(c0[0], c0[1], c0[2], c0[3], a0, a1, a2, a3, bh0, bh1);
                mma_bf16(c0[0], c0[1], c0[2], c0[3], a0, a1, a2, a3, bl0, bl1);
                mma_bf16(c0[0], c0[1], c0[2], c0[3], l0, l1, l2, l3, bh0, bh1);
                float* c1 = accr[p * 2 + 1];
                mma_bf16(c1[0], c1[1], c1[2], c1[3], a0, a1, a2, a3, bh2, bh3);
                mma_bf16(c1[0], c1[1], c1[2], c1[3], a0, a1, a2, a3, bl2, bl3);
                mma_bf16(c1[0], c1[1], c1[2], c1[3], l0, l1, l2, l3, bh2, bh3);
            }
        }
        __syncthreads();
        int kn = k0 + 64;
        if (kn < XKSL) X_ISSUE(cur, kn);
        CP_COMMIT;
        cur ^= 1;
    }

    const int row = bm + warp * 16 + g;
#pragma unroll
    for (int ni = 0; ni < 10; ni++) {
        int col = ni * 8 + cq * 2;
        float* c = accr[ni];
        atomicAdd(&out[(size_t)row * XDBL + col],           c[0]);
        atomicAdd(&out[(size_t)row * XDBL + col + 1],       c[1]);
        atomicAdd(&out[(size_t)(row + 8) * XDBL + col],     c[2]);
        atomicAdd(&out[(size_t)(row + 8) * XDBL + col + 1], c[3]);
    }
}
#undef X_ISSUE

// ---------------- causal depthwise conv (width 4) + silu -------------------
// emits fp32 xc (for scans) and bf16 hi/lo (for xproj tensor GEMM)
__global__ void conv_silu_kernel(const float* __restrict__ xz,
    const float* __restrict__ cw, const float* __restrict__ cb,
    float* __restrict__ xc, bf16* __restrict__ xch, bf16* __restrict__ xcl) {
    int idx = blockIdx.x * blockDim.x + threadIdx.x;
    if (idx >= BL * DINNER) return;
    int d  = idx % DINNER;
    int bl = idx / DINNER;
    int t  = bl % Lseq;
    float acc = cb[d];
#pragma unroll
    for (int j = 0; j < DCONV; j++) {
        int tt = t - (DCONV - 1) + j;
        if (tt >= 0)
            acc += cw[d * DCONV + j] *
                   xz[(size_t)(bl - (DCONV - 1) + j) * (2 * DINNER) + d];
    }
    float v = acc / (1.0f + __expf(-acc));
    xc[idx] = v;
    bf16 h = __float2bfloat16(v);
    xch[idx] = h;
    xcl[idx] = __float2bfloat16(v - __bfloat162float(h));
}

// ---------------- dt_proj + softplus ---------------------------------------
__global__ __launch_bounds__(256) void dtproj_kernel(const float* __restrict__ xdbl,
    const float* __restrict__ W, const float* __restrict__ bias,
    float* __restrict__ delta) {
    __shared__ float Xs[64][49];
    __shared__ float Ws[128][49];
    const int bm = blockIdx.x * 64, bn = blockIdx.y * 128;
    const int tid = threadIdx.x, tx = tid & 15, ty = tid >> 4;
    for (int e = tid; e < 64 * 48; e += 256) {
        int r = e / 48, c = e % 48;
        Xs[r][c] = xdbl[(size_t)(bm + r) * XDBL + c];
    }
    for (int e = tid; e < 128 * 48; e += 256) {
        int r = e / 48, c = e % 48;
        Ws[r][c] = W[(size_t)(bn + r) * DTRANK + c];
    }
    __syncthreads();
    float acc[4][8] = {};
    for (int k = 0; k < 48; k++) {
        float a[4], w[8];
#pragma unroll
        for (int rr = 0; rr < 4; rr++) a[rr] = Xs[ty + 16 * rr][k];
#pragma unroll
        for (int cc = 0; cc < 8; cc++) w[cc] = Ws[tx + 16 * cc][k];
#pragma unroll
        for (int rr = 0; rr < 4; rr++)
#pragma unroll
            for (int cc = 0; cc < 8; cc++)
                acc[rr][cc] += a[rr] * w[cc];
    }
#pragma unroll
    for (int rr = 0; rr < 4; rr++)
#pragma unroll
        for (int cc = 0; cc < 8; cc++) {
            int row = bm + ty + 16 * rr, col = bn + tx + 16 * cc;
            float v = acc[rr][cc] + bias[col];
            float sp = (v > 20.0f) ? v : log1pf(__expf(v));
            delta[(size_t)row * DINNER + col] = sp;
        }
}

// ---------------- chunked parallel scan -------------------------------------
__device__ __forceinline__ void pow_ladder(float e1, float* p) {
    float e2 = e1 * e1, e4 = e2 * e2, e8 = e4 * e4;
    p[0] = e1;        p[1] = e2;        p[2] = e2 * e1;   p[3] = e4;
    p[4] = e4 * e1;   p[5] = e4 * e2;   p[6] = e4 * p[2]; p[7] = e8;
    p[8] = e8 * e1;   p[9] = e8 * e2;   p[10] = e8 * p[2]; p[11] = e8 * e4;
    p[12] = e8 * p[4]; p[13] = e8 * p[5]; p[14] = e8 * p[6]; p[15] = e8 * e8;
}

// pass 1: per (b, chunk, d): P[n] = prod p_t[n], q[n] = scan offset
__global__ __launch_bounds__(256) void scan_pass1(const float* __restrict__ delta,
    const float* __restrict__ xc, const float* __restrict__ xdbl,
    const float* __restrict__ A_log,
    float* __restrict__ Pg, float* __restrict__ qg) {
    const int d = blockIdx.x * 256 + threadIdx.x;
    const int c = blockIdx.y, b = blockIdx.z;
    float a[DSTATE];
    bool fast = true;
#pragma unroll
    for (int n = 0; n < DSTATE; n++) a[n] = -expf(A_log[(size_t)d * DSTATE + n]);
#pragma unroll
    for (int n = 1; n < DSTATE; n++)
        fast = fast && (fabsf(a[n] / a[0] - (float)(n + 1)) < 1e-3f);

    __shared__ float Bsh[CLEN][DSTATE];
    for (int e = threadIdx.x; e < CLEN * DSTATE; e += 256) {
        int tt = e >> 4, n = e & 15;
        Bsh[tt][n] = xdbl[(size_t)(b * Lseq + c * CLEN + tt) * XDBL + DTRANK + n];
    }
    __syncthreads();

    float P[DSTATE], q[DSTATE];
#pragma unroll
    for (int n = 0; n < DSTATE; n++) { P[n] = 1.0f; q[n] = 0.0f; }

    for (int ti = 0; ti < CLEN; ti++) {
        const size_t ix = (size_t)(b * Lseq + c * CLEN + ti) * DINNER + d;
        const float dl = delta[ix];
        const float du = dl * xc[ix];
        float p[DSTATE];
        if (fast) pow_ladder(__expf(dl * a[0]), p);
        else {
#pragma unroll
            for (int n = 0; n < DSTATE; n++) p[n] = __expf(dl * a[n]);
        }
#pragma unroll
        for (int n = 0; n < DSTATE; n++) {
            q[n] = p[n] * q[n] + du * Bsh[ti][n];
            P[n] *= p[n];
        }
    }
    const size_t base = ((size_t)(b * NCH + c) * DSTATE) * DINNER + d;
#pragma unroll
    for (int n = 0; n < DSTATE; n++) {
        Pg[base + (size_t)n * DINNER] = P[n];
        qg[base + (size_t)n * DINNER] = q[n];
    }
}

// pass 2: prefix over chunks, parallel over (b, n, d)
__global__ __launch_bounds__(256) void scan_pass2(const float* __restrict__ Pg,
    const float* __restrict__ qg, float* __restrict__ hs) {
    const int idx = blockIdx.x * 256 + threadIdx.x;
    const int b = idx / (DSTATE * DINNER);
    const int rem = idx - b * DSTATE * DINNER;
    float h = 0.0f;
#pragma unroll 4
    for (int c = 0; c < NCH; c++) {
        const size_t o = ((size_t)(b * NCH + c) * DSTATE) * DINNER + rem;
        hs[o] = h;
        h = Pg[o] * h + qg[o];
    }
}

// pass 3: replay chunk from h_start, emit gated y (bf16 hi/lo)
__global__ __launch_bounds__(256) void scan_pass3(const float* __restrict__ delta,
    const float* __restrict__ xc, const float* __restrict__ xdbl,
    const float* __restrict__ xz, const float* __restrict__ A_log,
    const float* __restrict__ Dskip, const float* __restrict__ hs,
    bf16* __restrict__ yh, bf16* __restrict__ yl) {
    const int d = blockIdx.x * 256 + threadIdx.x;
    const int c = blockIdx.y, b = blockIdx.z;
    float a[DSTATE];
    bool fast = true;
#pragma unroll
    for (int n = 0; n < DSTATE; n++) a[n] = -expf(A_log[(size_t)d * DSTATE + n]);
#pragma unroll
    for (int n = 1; n < DSTATE; n++)
        fast = fast && (fabsf(a[n] / a[0] - (float)(n + 1)) < 1e-3f);
    const float dsk = Dskip[d];

    __shared__ float Bsh[CLEN][DSTATE];
    __shared__ float Csh[CLEN][DSTATE];
    for (int e = threadIdx.x; e < CLEN * DSTATE; e += 256) {
        int tt = e >> 4, n = e & 15;
        size_t rb = (size_t)(b * Lseq + c * CLEN + tt) * XDBL;
        Bsh[tt][n] = xdbl[rb + DTRANK + n];
        Csh[tt][n] = xdbl[rb + DTRANK + DSTATE + n];
    }
    __syncthreads();

    float h[DSTATE];
    const size_t base = ((size_t)(b * NCH + c) * DSTATE) * DINNER + d;
#pragma unroll
    for (int n = 0; n < DSTATE; n++) h[n] = hs[base + (size_t)n * DINNER];

    for (int ti = 0; ti < CLEN; ti++) {
        const size_t ix = (size_t)(b * Lseq + c * CLEN + ti) * DINNER + d;
        const float dl = delta[ix];
        const float u  = xc[ix];
        const float du = dl * u;
        float p[DSTATE];
        if (fast) pow_ladder(__expf(dl * a[0]), p);
        else {
#pragma unroll
            for (int n = 0; n < DSTATE; n++) p[n] = __expf(dl * a[n]);
        }
        float ys = 0.0f;
#pragma unroll
        for (int n = 0; n < DSTATE; n++) {
            h[n] = p[n] * h[n] + du * Bsh[ti][n];
            ys += h[n] * Csh[ti][n];
        }
        const float z = xz[(size_t)(b * Lseq + c * CLEN + ti) * (2 * DINNER) + DINNER + d];
        const float g = z / (1.0f + __expf(-z));
        float v = (ys + u * dsk) * g;
        bf16 hi = __float2bfloat16(v);
        yh[ix] = hi;
        yl[ix] = __float2bfloat16(v - __bfloat162float(hi));
    }
}

// ---------------- final norm + MLP head (tiny), fused ----------------------
__device__ __forceinline__ float gelu_exact(float x) {
    return 0.5f * x * (1.0f + erff(x * 0.70710678118654752f));
}

__global__ __launch_bounds__(256) void head_kernel(const float* __restrict__ res,
    const float* __restrict__ fnw, const float* __restrict__ h1w,
    const float* __restrict__ h1b, const float* __restrict__ hnw,
    const float* __restrict__ h2w, const float* __restrict__ h2b,
    float* __restrict__ out) {
    __shared__ float xs[768];
    __shared__ float hsm[768];
    __shared__ float red[256];
    const int b = blockIdx.x;
    const int tid = threadIdx.x;
    const int warp = tid >> 5, lane = tid & 31;

    const float* xr = res + ((size_t)b * Lseq + (Lseq - 1)) * Dm;
    float v0 = xr[tid], v1 = xr[tid + 256], v2 = xr[tid + 512];
    red[tid] = v0 * v0 + v1 * v1 + v2 * v2;
    __syncthreads();
    for (int s = 128; s > 0; s >>= 1) {
        if (tid < s) red[tid] += red[tid + s];
        __syncthreads();
    }
    float rinv = rsqrtf(red[0] * (1.0f / Dm) + 1e-6f);
    xs[tid]       = v0 * rinv * fnw[tid];
    xs[tid + 256] = v1 * rinv * fnw[tid + 256];
    xs[tid + 512] = v2 * rinv * fnw[tid + 512];
    __syncthreads();

    for (int o = warp; o < 768; o += 8) {
        const float* wr = h1w + (size_t)o * 768;
        float p = 0.0f;
        for (int j = lane; j < 768; j += 32) p += wr[j] * xs[j];
#pragma unroll
        for (int s = 16; s > 0; s >>= 1) p += __shfl_xor_sync(0xffffffff, p, s);
        if (lane == 0) hsm[o] = p + h1b[o];
    }
    __syncthreads();

    float h0 = hsm[tid], h1v = hsm[tid + 256], h2v = hsm[tid + 512];
    red[tid] = h0 * h0 + h1v * h1v + h2v * h2v;
    __syncthreads();
    for (int s = 128; s > 0; s >>= 1) {
        if (tid < s) red[tid] += red[tid + s];
        __syncthreads();
    }
    float rinv2 = rsqrtf(red[0] * (1.0f / Dm) + 1e-6f);
    hsm[tid]       = gelu_exact(h0  * rinv2 * hnw[tid]);
    hsm[tid + 256] = gelu_exact(h1v * rinv2 * hnw[tid + 256]);
    hsm[tid + 512] = gelu_exact(h2v * rinv2 * hnw[tid + 512]);
    __syncthreads();

    for (int o = warp; o < NCLS; o += 8) {
        const float* wr = h2w + (size_t)o * 768;
        float p = 0.0f;
        for (int j = lane; j < 768; j += 32) p += wr[j] * hsm[j];
#pragma unroll
        for (int s = 16; s > 0; s >>= 1) p += __shfl_xor_sync(0xffffffff, p, s);
        if (lane == 0) out[b * NCLS + o] = p + h2b[o];
    }
}

// ---------------- launch ---------------------------------------------------
extern "C" void kernel_launch(void* const* d_in, const int* in_sizes, int n_in,
                              void* d_out, int out_size) {
    const float* x           = (const float*)d_in[0];
    const float* norm_w      = (const float*)d_in[1];
    const float* in_proj_w   = (const float*)d_in[2];
    const float* conv_w      = (const float*)d_in[3];
    const float* conv_b      = (const float*)d_in[4];
    const float* x_proj_w    = (const float*)d_in[5];
    const float* dt_proj_w   = (const float*)d_in[6];
    const float* dt_proj_b   = (const float*)d_in[7];
    const float* A_log       = (const float*)d_in[8];
    const float* D_skip      = (const float*)d_in[9];
    const float* out_proj_w  = (const float*)d_in[10];
    const float* final_norm_w= (const float*)d_in[11];
    const float* head1_w     = (const float*)d_in[12];
    const float* head1_b     = (const float*)d_in[13];
    const float* head_norm_w = (const float*)d_in[14];
    const float* head2_w     = (const float*)d_in[15];
    const float* head2_b     = (const float*)d_in[16];
    float* out = (float*)d_out;

    float *res, *xzp, *xcp, *xdblp, *deltap, *Pg, *qg, *hsg;
    bf16 *xnh, *xnl, *xch, *xcl, *yh, *yl, *wih, *wil, *woh, *wol, *wxh, *wxl;
    cudaGetSymbolAddress((void**)&res,    g_res);
    cudaGetSymbolAddress((void**)&xnh,    g_xnh);
    cudaGetSymbolAddress((void**)&xnl,    g_xnl);
    cudaGetSymbolAddress((void**)&xzp,    g_xz);
    cudaGetSymbolAddress((void**)&xcp,    g_xc);
    cudaGetSymbolAddress((void**)&xch,    g_xch);
    cudaGetSymbolAddress((void**)&xcl,    g_xcl);
    cudaGetSymbolAddress((void**)&xdblp,  g_xdbl);
    cudaGetSymbolAddress((void**)&deltap, g_delta);
    cudaGetSymbolAddress((void**)&yh,     g_yh);
    cudaGetSymbolAddress((void**)&yl,     g_yl);
    cudaGetSymbolAddress((void**)&Pg,     g_P);
    cudaGetSymbolAddress((void**)&qg,     g_q);
    cudaGetSymbolAddress((void**)&hsg,    g_hs);
    cudaGetSymbolAddress((void**)&wih,    g_wih);
    cudaGetSymbolAddress((void**)&wil,    g_wil);
    cudaGetSymbolAddress((void**)&woh,    g_woh);
    cudaGetSymbolAddress((void**)&wol,    g_wol);
    cudaGetSymbolAddress((void**)&wxh,    g_wxh);
    cudaGetSymbolAddress((void**)&wxl,    g_wxl);

    // dynamic smem opt-ins (idempotent)
    cudaFuncSetAttribute(gemm_bf16x2,
        cudaFuncAttributeMaxDynamicSharedMemorySize, GSTAGES * STAGEB);
    cudaFuncSetAttribute(xproj_tc,
        cudaFuncAttributeMaxDynamicSharedMemorySize, 2 * XSTAGEB);
    const int GSMEM = GSTAGES * STAGEB;
    const int XSMEM = 2 * XSTAGEB;

    cudaMemcpyAsync(res, x, sizeof(float) * BL * Dm, cudaMemcpyDeviceToDevice, 0);

    cvt_split_kernel<<<592, 256>>>(in_proj_w,  wih, wil, NLAYERS * 2 * DINNER * Dm);
    cvt_split_kernel<<<592, 256>>>(out_proj_w, woh, wol, NLAYERS * Dm * DINNER);
    cvt_split_kernel<<<240, 256>>>(x_proj_w,   wxh, wxl, NLAYERS * XDBL * DINNER);

    for (int i = 0; i < NLAYERS; i++) {
        rmsnorm_kernel<<<BL, 256>>>(res, norm_w + (size_t)i * Dm, xnh, xnl);

        // in_proj: single-K, plain store (reverted from split-K)
        dim3 g1(2 * DINNER / 128, BL / 128, 1);
        gemm_bf16x2<<<g1, 256, GSMEM>>>(xnh, xnl,
                                 wih + (size_t)i * 2 * DINNER * Dm,
                                 wil + (size_t)i * 2 * DINNER * Dm,
                                 xzp, 2 * DINNER, Dm, Dm, 0);

        conv_silu_kernel<<<BL * DINNER / 256, 256>>>(
            xzp, conv_w + (size_t)i * DINNER * DCONV, conv_b + (size_t)i * DINNER,
            xcp, xch, xcl);

        cudaMemsetAsync(xdblp, 0, sizeof(float) * BL * XDBL, 0);
        dim3 g2(XSPLIT, BL / 128);
        xproj_tc<<<g2, 256, XSMEM>>>(xch, xcl,
                                     wxh + (size_t)i * XDBL * DINNER,
                                     wxl + (size_t)i * XDBL * DINNER, xdblp);

        dim3 g3(BL / 64, DINNER / 128);
        dtproj_kernel<<<g3, 256>>>(xdblp, dt_proj_w + (size_t)i * DINNER * DTRANK,
                                   dt_proj_b + (size_t)i * DINNER, deltap);

        const float* Alog_i = A_log + (size_t)i * DINNER * DSTATE;
        dim3 gs(DINNER / 256, NCH, Bsz);
        scan_pass1<<<gs, 256>>>(deltap, xcp, xdblp, Alog_i, Pg, qg);
        scan_pass2<<<Bsz * DSTATE * DINNER / 256, 256>>>(Pg, qg, hsg);
        scan_pass3<<<gs, 256>>>(deltap, xcp, xdblp, xzp, Alog_i,
                                D_skip + (size_t)i * DINNER, hsg, yh, yl);

        // out_proj: split-K 8-way, atomicAdd accumulation onto residual
        dim3 g5(Dm / 128, BL / 128, 8);
        gemm_bf16x2<<<g5, 256, GSMEM>>>(yh, yl,
                                 woh + (size_t)i * Dm * DINNER,
                                 wol + (size_t)i * Dm * DINNER,
                                 res, Dm, DINNER, DINNER / 8, 1);
    }

    head_kernel<<<Bsz, 256>>>(res, final_norm_w, head1_w, head1_b,
                              head_norm_w, head2_w, head2_b, out);
}